// round 7
// baseline (speedup 1.0000x reference)
#include <cuda_runtime.h>
#include <math.h>

// ---------------------------------------------------------------------------
// Problem constants
// ---------------------------------------------------------------------------
#define BATCH   2
#define SEQ     2048
#define DMODEL  1024
#define HEADS   16
#define DK      64
#define NTOK    (BATCH * SEQ)        // 4096

// ---------------------------------------------------------------------------
// Scratch (device globals — no allocation allowed)
// ---------------------------------------------------------------------------
__device__ float g_Q  [(size_t)NTOK * DMODEL];
__device__ float g_K  [(size_t)NTOK * DMODEL];
__device__ float g_V  [(size_t)NTOK * DMODEL];
__device__ float g_CTX[(size_t)NTOK * DMODEL];
__device__ float g_cos[SEQ * (DK / 2)];
__device__ float g_sin[SEQ * (DK / 2)];

// ---------------------------------------------------------------------------
// RoPE table: mimic reference fp32 rounding of the angle, accurate trig.
// ---------------------------------------------------------------------------
__global__ void rope_table_kernel(float* __restrict__ cosT, float* __restrict__ sinT)
{
    int idx = blockIdx.x * blockDim.x + threadIdx.x;
    if (idx >= SEQ * (DK / 2)) return;
    int s = idx >> 5;          // position
    int i = idx & 31;          // pair index
    double inv = pow(10000.0, -((double)(2 * i) / (double)DK));
    float  invf = (float)inv;                 // fp32 inv_freq (as reference)
    float  ang  = (float)s * invf;            // fp32 angle (as reference)
    cosT[idx] = (float)cos((double)ang);
    sinT[idx] = (float)sin((double)ang);
}

// ---------------------------------------------------------------------------
// SGEMM  C[M,N] = A[M,K] * B[N,K]^T   (both row-major, K contiguous)
// 128x128 tile, BK=16, 256 threads, 8x8 per thread.
// Optional fused interleaved-pair RoPE on the output (per head of 64 cols).
// ---------------------------------------------------------------------------
#define GM 128
#define GN 128
#define GK 16

template<bool ROPE>
__global__ __launch_bounds__(256)
void gemm_nt_kernel(const float* __restrict__ A, const float* __restrict__ Bw,
                    float* __restrict__ C, int M, int N, int K,
                    const float* __restrict__ cosT, const float* __restrict__ sinT)
{
    __shared__ float As[GK][GM];
    __shared__ float Bs[GK][GN];

    const int tid = threadIdx.x;
    const int tx  = tid & 15;
    const int ty  = tid >> 4;
    const int m0  = blockIdx.y * GM;
    const int n0  = blockIdx.x * GN;

    float acc[8][8];
#pragma unroll
    for (int i = 0; i < 8; ++i)
#pragma unroll
        for (int j = 0; j < 8; ++j) acc[i][j] = 0.f;

    // global-load mapping: 128 rows x 16 cols = 512 float4; 2 per thread
    const int lr = tid >> 2;            // 0..63
    const int lc = (tid & 3) * 4;       // 0,4,8,12

    const float* Ap = A  + (size_t)(m0 + lr) * K + lc;
    const float* Bp = Bw + (size_t)(n0 + lr) * K + lc;
    const size_t half = (size_t)64 * K;

    for (int k0 = 0; k0 < K; k0 += GK) {
        float4 a0 = *(const float4*)(Ap + k0);
        float4 a1 = *(const float4*)(Ap + k0 + half);
        float4 b0 = *(const float4*)(Bp + k0);
        float4 b1 = *(const float4*)(Bp + k0 + half);

        __syncthreads();
        As[lc + 0][lr]      = a0.x; As[lc + 1][lr]      = a0.y;
        As[lc + 2][lr]      = a0.z; As[lc + 3][lr]      = a0.w;
        As[lc + 0][lr + 64] = a1.x; As[lc + 1][lr + 64] = a1.y;
        As[lc + 2][lr + 64] = a1.z; As[lc + 3][lr + 64] = a1.w;
        Bs[lc + 0][lr]      = b0.x; Bs[lc + 1][lr]      = b0.y;
        Bs[lc + 2][lr]      = b0.z; Bs[lc + 3][lr]      = b0.w;
        Bs[lc + 0][lr + 64] = b1.x; Bs[lc + 1][lr + 64] = b1.y;
        Bs[lc + 2][lr + 64] = b1.z; Bs[lc + 3][lr + 64] = b1.w;
        __syncthreads();

#pragma unroll
        for (int k = 0; k < GK; ++k) {
            float4 ra0 = *(const float4*)&As[k][ty * 4];
            float4 ra1 = *(const float4*)&As[k][ty * 4 + 64];
            float4 rb0 = *(const float4*)&Bs[k][tx * 4];
            float4 rb1 = *(const float4*)&Bs[k][tx * 4 + 64];
            float av[8] = {ra0.x, ra0.y, ra0.z, ra0.w, ra1.x, ra1.y, ra1.z, ra1.w};
            float bv[8] = {rb0.x, rb0.y, rb0.z, rb0.w, rb1.x, rb1.y, rb1.z, rb1.w};
#pragma unroll
            for (int i = 0; i < 8; ++i)
#pragma unroll
                for (int j = 0; j < 8; ++j)
                    acc[i][j] = fmaf(av[i], bv[j], acc[i][j]);
        }
    }

    // epilogue
#pragma unroll
    for (int i = 0; i < 8; ++i) {
        const int r = ((i & 4) << 4) + ty * 4 + (i & 3);   // i<4: ty*4+i, else +64
        const int m = m0 + r;
#pragma unroll
        for (int cb = 0; cb < 2; ++cb) {
            const int n = n0 + cb * 64 + tx * 4;
            float4 o;
            o.x = acc[i][cb * 4 + 0];
            o.y = acc[i][cb * 4 + 1];
            o.z = acc[i][cb * 4 + 2];
            o.w = acc[i][cb * 4 + 3];
            if (ROPE) {
                const int pos = m & (SEQ - 1);
                const int i0  = (n & 63) >> 1;        // pair index for (x,y)
                const float c0 = cosT[pos * 32 + i0];
                const float s0 = sinT[pos * 32 + i0];
                const float c1 = cosT[pos * 32 + i0 + 1];
                const float s1 = sinT[pos * 32 + i0 + 1];
                float x = o.x, y = o.y, z = o.z, w = o.w;
                o.x = x * c0 - y * s0;
                o.y = y * c0 + x * s0;
                o.z = z * c1 - w * s1;
                o.w = w * c1 + z * s1;
            }
            *(float4*)(C + (size_t)m * N + n) = o;
        }
    }
}

// ---------------------------------------------------------------------------
// Flash attention (causal), fp32. 64x64 tiles, 256 threads, 4x4 per thread.
// Q/K/V/O are token-major [NTOK, DMODEL] with head h at columns h*64..h*64+63.
// ---------------------------------------------------------------------------
#define PADK 65
#define ATTN_SMEM_FLOATS (3 * 64 * PADK + 64 * 64)
#define ATTN_SMEM_BYTES  (ATTN_SMEM_FLOATS * 4)

__global__ __launch_bounds__(256)
void attn_kernel(const float* __restrict__ Q, const float* __restrict__ K,
                 const float* __restrict__ V, float* __restrict__ O)
{
    extern __shared__ float sm[];
    float* Qs = sm;                       // [64][65]
    float* Ks = sm + 64 * PADK;           // [64][65]
    float* Ps = sm + 2 * 64 * PADK;       // [64][65]
    float* Vs = sm + 3 * 64 * PADK;       // [64][64]

    const int tid = threadIdx.x;
    const int tx  = tid & 15;
    const int ty  = tid >> 4;
    const int qt  = blockIdx.x;           // q tile 0..31
    const int bh  = blockIdx.y;           // 0..31
    const int b   = bh >> 4;
    const int h   = bh & 15;
    const int q0  = qt * 64;

    const size_t base = ((size_t)b * SEQ) * DMODEL + (size_t)h * DK;
    const float* Qg = Q + base;
    const float* Kg = K + base;
    const float* Vg = V + base;
    float*       Og = O + base;

    // load Q tile, pre-scaled by 1/sqrt(Dk) = 0.125
#pragma unroll
    for (int it = 0; it < 4; ++it) {
        int f   = tid + it * 256;
        int row = f >> 4;
        int c4  = (f & 15) << 2;
        float4 v = *(const float4*)(Qg + (size_t)(q0 + row) * DMODEL + c4);
        float* dst = Qs + row * PADK + c4;
        dst[0] = v.x * 0.125f; dst[1] = v.y * 0.125f;
        dst[2] = v.z * 0.125f; dst[3] = v.w * 0.125f;
    }

    float m_[4], l_[4], acc[4][4];
#pragma unroll
    for (int i = 0; i < 4; ++i) {
        m_[i] = -1e30f; l_[i] = 0.f;
#pragma unroll
        for (int j = 0; j < 4; ++j) acc[i][j] = 0.f;
    }

    for (int j = 0; j <= qt; ++j) {
        const int kv0 = j * 64;
        __syncthreads();   // previous iteration's smem reads complete
#pragma unroll
        for (int it = 0; it < 4; ++it) {
            int f   = tid + it * 256;
            int row = f >> 4;
            int c4  = (f & 15) << 2;
            float4 kv = *(const float4*)(Kg + (size_t)(kv0 + row) * DMODEL + c4);
            float* kd = Ks + row * PADK + c4;
            kd[0] = kv.x; kd[1] = kv.y; kd[2] = kv.z; kd[3] = kv.w;
            float4 vv = *(const float4*)(Vg + (size_t)(kv0 + row) * DMODEL + c4);
            *(float4*)(Vs + row * 64 + c4) = vv;
        }
        __syncthreads();

        // scores S = (Q/8) K^T
        float s[4][4];
#pragma unroll
        for (int i = 0; i < 4; ++i)
#pragma unroll
            for (int jj = 0; jj < 4; ++jj) s[i][jj] = 0.f;

#pragma unroll 16
        for (int d = 0; d < DK; ++d) {
            float qv[4], kv_[4];
#pragma unroll
            for (int i = 0; i < 4; ++i)  qv[i]  = Qs[(ty * 4 + i) * PADK + d];
#pragma unroll
            for (int jj = 0; jj < 4; ++jj) kv_[jj] = Ks[(tx * 4 + jj) * PADK + d];
#pragma unroll
            for (int i = 0; i < 4; ++i)
#pragma unroll
                for (int jj = 0; jj < 4; ++jj)
                    s[i][jj] = fmaf(qv[i], kv_[jj], s[i][jj]);
        }

        // causal mask (only the diagonal tile can have masked entries)
        if (j == qt) {
#pragma unroll
            for (int i = 0; i < 4; ++i)
#pragma unroll
                for (int jj = 0; jj < 4; ++jj)
                    if (kv0 + tx * 4 + jj > q0 + ty * 4 + i) s[i][jj] = -1e30f;
        }

        // online softmax, per row
#pragma unroll
        for (int i = 0; i < 4; ++i) {
            float rm = fmaxf(fmaxf(s[i][0], s[i][1]), fmaxf(s[i][2], s[i][3]));
#pragma unroll
            for (int off = 1; off < 16; off <<= 1)
                rm = fmaxf(rm, __shfl_xor_sync(0xffffffffu, rm, off));
            float mn    = fmaxf(m_[i], rm);
            float alpha = __expf(m_[i] - mn);
            float rs = 0.f;
#pragma unroll
            for (int jj = 0; jj < 4; ++jj) {
                s[i][jj] = __expf(s[i][jj] - mn);
                rs += s[i][jj];
            }
#pragma unroll
            for (int off = 1; off < 16; off <<= 1)
                rs += __shfl_xor_sync(0xffffffffu, rs, off);
            l_[i] = l_[i] * alpha + rs;
            m_[i] = mn;
#pragma unroll
            for (int jj = 0; jj < 4; ++jj) acc[i][jj] *= alpha;
            // stage P
            float* pd = Ps + (ty * 4 + i) * PADK + tx * 4;
            pd[0] = s[i][0]; pd[1] = s[i][1]; pd[2] = s[i][2]; pd[3] = s[i][3];
        }
        __syncthreads();

        // O += P @ V
#pragma unroll 16
        for (int k = 0; k < 64; ++k) {
            float pv[4], vv[4];
#pragma unroll
            for (int i = 0; i < 4; ++i)  pv[i] = Ps[(ty * 4 + i) * PADK + k];
#pragma unroll
            for (int jj = 0; jj < 4; ++jj) vv[jj] = Vs[k * 64 + tx * 4 + jj];
#pragma unroll
            for (int i = 0; i < 4; ++i)
#pragma unroll
                for (int jj = 0; jj < 4; ++jj)
                    acc[i][jj] = fmaf(pv[i], vv[jj], acc[i][jj]);
        }
    }

    // epilogue: normalize and store
#pragma unroll
    for (int i = 0; i < 4; ++i) {
        float inv = 1.f / l_[i];
        float4 o;
        o.x = acc[i][0] * inv; o.y = acc[i][1] * inv;
        o.z = acc[i][2] * inv; o.w = acc[i][3] * inv;
        *(float4*)(Og + (size_t)(q0 + ty * 4 + i) * DMODEL + tx * 4) = o;
    }
}

// ---------------------------------------------------------------------------
// Launch
// ---------------------------------------------------------------------------
extern "C" void kernel_launch(void* const* d_in, const int* in_sizes, int n_in,
                              void* d_out, int out_size)
{
    const float* x  = (const float*)d_in[0];
    const float* wq = (const float*)d_in[1];
    const float* wk = (const float*)d_in[2];
    const float* wv = (const float*)d_in[3];
    const float* wo = (const float*)d_in[4];
    float* out = (float*)d_out;

    float *Qb, *Kb, *Vb, *Cb, *cT, *sT;
    cudaGetSymbolAddress((void**)&Qb, g_Q);
    cudaGetSymbolAddress((void**)&Kb, g_K);
    cudaGetSymbolAddress((void**)&Vb, g_V);
    cudaGetSymbolAddress((void**)&Cb, g_CTX);
    cudaGetSymbolAddress((void**)&cT, g_cos);
    cudaGetSymbolAddress((void**)&sT, g_sin);

    cudaFuncSetAttribute(attn_kernel,
                         cudaFuncAttributeMaxDynamicSharedMemorySize,
                         ATTN_SMEM_BYTES);

    rope_table_kernel<<<(SEQ * 32 + 255) / 256, 256>>>(cT, sT);

    dim3 gg(DMODEL / GN, NTOK / GM);   // (8, 32)
    gemm_nt_kernel<true ><<<gg, 256>>>(x,  wq, Qb, NTOK, DMODEL, DMODEL, cT, sT);
    gemm_nt_kernel<true ><<<gg, 256>>>(x,  wk, Kb, NTOK, DMODEL, DMODEL, cT, sT);
    gemm_nt_kernel<false><<<gg, 256>>>(x,  wv, Vb, NTOK, DMODEL, DMODEL, cT, sT);

    attn_kernel<<<dim3(SEQ / 64, BATCH * HEADS), 256, ATTN_SMEM_BYTES>>>(Qb, Kb, Vb, Cb);

    gemm_nt_kernel<false><<<gg, 256>>>(Cb, wo, out, NTOK, DMODEL, DMODEL, cT, sT);
}